// round 5
// baseline (speedup 1.0000x reference)
#include <cuda_runtime.h>
#include <cuda_bf16.h>
#include <cstddef>

// Problem constants
#define S_LEN  2048
#define EMB    1024
#define NH     16
#define HD     64
#define BATCH  2
#define MROWS  (BATCH * S_LEN)   // 4096

// Scratch in device globals (no allocation allowed)
__device__ float g_q[(size_t)BATCH * NH * S_LEN * HD];
__device__ float g_k[(size_t)BATCH * NH * S_LEN * HD];
__device__ float g_v[(size_t)BATCH * NH * S_LEN * HD];
__device__ float g_ctx[(size_t)BATCH * S_LEN * EMB];

// ---------------------------------------------------------------------------
// Tiled fp32 GEMM: C[M,N] = A[M,K] @ W[K,N] (+bias)
// M=4096, N=K=1024. BM=BN=128, BK=16, 256 threads, 8x8 per-thread microtile.
// MODE 0: C[row*N+col] = acc + bias[col]           (row-major output)
// MODE 1: write to [B, H, S, D] layout (head split) (no bias)
// ---------------------------------------------------------------------------
template <int MODE>
__global__ __launch_bounds__(256) void gemm_k(const float* __restrict__ A,
                                              const float* __restrict__ W,
                                              const float* __restrict__ bias,
                                              float* __restrict__ C)
{
    const int K = EMB, N = EMB;
    __shared__ float As[16][128];   // transposed A tile: As[k][m]
    __shared__ float Ws[16][128];   // Ws[k][n]

    const int tid = threadIdx.x;
    const int bm = blockIdx.y * 128;
    const int bn = blockIdx.x * 128;
    const int tx = tid & 15;        // 0..15 -> n
    const int ty = tid >> 4;        // 0..15 -> m

    float c[8][8];
#pragma unroll
    for (int i = 0; i < 8; i++)
#pragma unroll
        for (int j = 0; j < 8; j++) c[i][j] = 0.f;

    for (int k0 = 0; k0 < K; k0 += 16) {
        // Load A tile (128 rows x 16 cols), store transposed
#pragma unroll
        for (int i = 0; i < 2; i++) {
            int row = (tid >> 2) + i * 64;       // 0..127
            int kc  = (tid & 3) << 2;            // 0,4,8,12
            float4 a = *(const float4*)(A + (size_t)(bm + row) * K + k0 + kc);
            As[kc + 0][row] = a.x;
            As[kc + 1][row] = a.y;
            As[kc + 2][row] = a.z;
            As[kc + 3][row] = a.w;
        }
        // Load W tile (16 rows x 128 cols)
#pragma unroll
        for (int i = 0; i < 2; i++) {
            int kr = (tid >> 5) + i * 8;         // 0..15
            int nc = (tid & 31) << 2;            // 0..124
            *(float4*)&Ws[kr][nc] =
                *(const float4*)(W + (size_t)(k0 + kr) * N + bn + nc);
        }
        __syncthreads();

#pragma unroll
        for (int k = 0; k < 16; k++) {
            float a[8], b[8];
            *(float4*)(a + 0) = *(float4*)&As[k][(ty << 3) + 0];
            *(float4*)(a + 4) = *(float4*)&As[k][(ty << 3) + 4];
            *(float4*)(b + 0) = *(float4*)&Ws[k][(tx << 3) + 0];
            *(float4*)(b + 4) = *(float4*)&Ws[k][(tx << 3) + 4];
#pragma unroll
            for (int i = 0; i < 8; i++)
#pragma unroll
                for (int j = 0; j < 8; j++) c[i][j] += a[i] * b[j];
        }
        __syncthreads();
    }

    // Epilogue
#pragma unroll
    for (int i = 0; i < 8; i++) {
        int row = bm + (ty << 3) + i;
#pragma unroll
        for (int j = 0; j < 8; j += 4) {
            int col = bn + (tx << 3) + j;
            float4 v;
            v.x = c[i][j + 0];
            v.y = c[i][j + 1];
            v.z = c[i][j + 2];
            v.w = c[i][j + 3];
            if (MODE == 0) {
                v.x += bias[col + 0];
                v.y += bias[col + 1];
                v.z += bias[col + 2];
                v.w += bias[col + 3];
                *(float4*)&C[(size_t)row * N + col] = v;
            } else {
                int b_ = row >> 11;         // row / S_LEN
                int s  = row & (S_LEN - 1);
                int h  = col >> 6;          // col / HD
                int d  = col & (HD - 1);
                size_t off = ((((size_t)b_ * NH + h) * S_LEN) + s) * HD + d;
                *(float4*)&C[off] = v;
            }
        }
    }
}

// ---------------------------------------------------------------------------
// Flash attention (causal), fp32. One thread owns one query row fully.
// Block = 128 threads = 128 query rows. K/V tiles of 32 rows x 64 in SMEM.
// grid = (S/128, B*H)
// ---------------------------------------------------------------------------
__global__ __launch_bounds__(128) void flash_k(const float* __restrict__ Q,
                                               const float* __restrict__ Kg,
                                               const float* __restrict__ Vg,
                                               float* __restrict__ O)
{
    __shared__ float Ks[32][64];
    __shared__ float Vs[32][64];

    const int qt  = blockIdx.x;   // 0..15
    const int bh  = blockIdx.y;   // 0..31
    const int tid = threadIdx.x;
    const int qrow = qt * 128 + tid;

    const float* qp = Q + ((size_t)bh * S_LEN + qrow) * HD;
    float q[64];
#pragma unroll
    for (int i = 0; i < 16; i++)
        *(float4*)&q[i * 4] = *(const float4*)(qp + i * 4);

    float acc[64];
#pragma unroll
    for (int d = 0; d < 64; d++) acc[d] = 0.f;
    float m = -1e30f, l = 0.f;

    const int ntiles = 4 * qt + 4;  // covers keys 0 .. qt*128+127 (causal)
    const float* kbase_p = Kg + (size_t)bh * S_LEN * HD;
    const float* vbase_p = Vg + (size_t)bh * S_LEN * HD;

    for (int kt = 0; kt < ntiles; kt++) {
        __syncthreads();
        // load K,V tiles: 32*64 = 2048 floats each = 512 float4 each
        const float4* ksrc = (const float4*)(kbase_p + (size_t)kt * 32 * 64);
        const float4* vsrc = (const float4*)(vbase_p + (size_t)kt * 32 * 64);
#pragma unroll
        for (int i = 0; i < 4; i++) {
            int idx = tid + i * 128;
            ((float4*)Ks)[idx] = ksrc[idx];
            ((float4*)Vs)[idx] = vsrc[idx];
        }
        __syncthreads();

        const int kb = kt * 32;
        float sc[32];
#pragma unroll
        for (int k = 0; k < 32; k++) {
            float s = 0.f;
#pragma unroll
            for (int d = 0; d < 64; d += 4) {
                float4 kk = *(const float4*)&Ks[k][d];
                s += q[d + 0] * kk.x + q[d + 1] * kk.y +
                     q[d + 2] * kk.z + q[d + 3] * kk.w;
            }
            s *= 0.125f;  // 1/sqrt(64)
            sc[k] = (kb + k > qrow) ? -1e30f : s;
        }

        float mt = m;
#pragma unroll
        for (int k = 0; k < 32; k++) mt = fmaxf(mt, sc[k]);
        float corr = __expf(m - mt);
        float sum = 0.f;
#pragma unroll
        for (int k = 0; k < 32; k++) {
            sc[k] = __expf(sc[k] - mt);
            sum += sc[k];
        }
        l = l * corr + sum;
#pragma unroll
        for (int d = 0; d < 64; d++) acc[d] *= corr;
#pragma unroll
        for (int k = 0; k < 32; k++) {
            float p = sc[k];
#pragma unroll
            for (int d = 0; d < 64; d += 4) {
                float4 vv = *(const float4*)&Vs[k][d];
                acc[d + 0] += p * vv.x;
                acc[d + 1] += p * vv.y;
                acc[d + 2] += p * vv.z;
                acc[d + 3] += p * vv.w;
            }
        }
        m = mt;
    }

    const float inv = 1.f / l;
    const int b_ = bh >> 4;
    const int h  = bh & 15;
    float* op = O + ((size_t)b_ * S_LEN + qrow) * EMB + h * HD;
#pragma unroll
    for (int d = 0; d < 64; d += 4) {
        float4 v;
        v.x = acc[d + 0] * inv;
        v.y = acc[d + 1] * inv;
        v.z = acc[d + 2] * inv;
        v.w = acc[d + 3] * inv;
        *(float4*)(op + d) = v;
    }
}

// ---------------------------------------------------------------------------
extern "C" void kernel_launch(void* const* d_in, const int* in_sizes, int n_in,
                              void* d_out, int out_size)
{
    const float* x  = (const float*)d_in[0];
    const float* Wq = (const float*)d_in[1];
    const float* Wk = (const float*)d_in[2];
    const float* Wv = (const float*)d_in[3];
    const float* Wo = (const float*)d_in[4];
    const float* bo = (const float*)d_in[5];
    float* out = (float*)d_out;

    float *qb, *kb, *vb, *cb;
    cudaGetSymbolAddress((void**)&qb, g_q);
    cudaGetSymbolAddress((void**)&kb, g_k);
    cudaGetSymbolAddress((void**)&vb, g_v);
    cudaGetSymbolAddress((void**)&cb, g_ctx);

    dim3 gg(EMB / 128, MROWS / 128);  // (8, 32)

    gemm_k<1><<<gg, 256>>>(x, Wq, nullptr, qb);
    gemm_k<1><<<gg, 256>>>(x, Wk, nullptr, kb);
    gemm_k<1><<<gg, 256>>>(x, Wv, nullptr, vb);

    flash_k<<<dim3(S_LEN / 128, BATCH * NH), 128>>>(qb, kb, vb, cb);

    gemm_k<0><<<gg, 256>>>(cb, Wo, bo, out);
}